// round 1
// baseline (speedup 1.0000x reference)
#include <cuda_runtime.h>
#include <cuda_bf16.h>
#include <cstdint>

// Problem dims
#define BB 4
#define TT 512
#define DD 512
#define HH 1024
#define VV 32000
#define MM (BB*TT)                 // 2048 rows
#define NLOGITS ((long long)MM * VV)  // 65,536,000

#define DECAYF 0.60653065971263342f  // exp(-1/2)

// ---------------- scratch (static device allocations are allowed) -----------
__device__ float g_u[MM * HH];        // fc1 output, 8 MB
__device__ int   g_cnt[MM];           // spikes per (b,t) row
__device__ int   g_list[MM * HH];     // spike h-indices per row (worst case full)

// ---------------- K0: zero the counters ------------------------------------
__global__ void zero_cnt_kernel() {
    int i = blockIdx.x * blockDim.x + threadIdx.x;
    if (i < MM) g_cnt[i] = 0;
}

// ---------------- K1: fused gather + fc1 SGEMM ------------------------------
// u[m, h] = sum_d emb[ids[m], d] * W1[h, d] + b1[h]
// BM=64, BN=64, BK=16, 256 threads, 4x4 per-thread tile
#define BM 64
#define BN 64
#define BK 16
__global__ __launch_bounds__(256) void fc1_kernel(
    const int* __restrict__ ids, const float* __restrict__ emb,
    const float* __restrict__ W1, const float* __restrict__ b1)
{
    __shared__ float As[BK][BM];
    __shared__ float Bs[BK][BN];
    __shared__ int   sids[BM];

    const int bn = blockIdx.x * BN;   // h offset
    const int bm = blockIdx.y * BM;   // row offset
    const int tid = threadIdx.x;
    const int tx = tid & 15;          // 0..15 -> 4 cols each
    const int ty = tid >> 4;          // 0..15 -> 4 rows each

    if (tid < BM) sids[tid] = ids[bm + tid];
    __syncthreads();

    float acc[4][4];
#pragma unroll
    for (int i = 0; i < 4; i++)
#pragma unroll
        for (int j = 0; j < 4; j++) acc[i][j] = 0.f;

    const int lm = tid >> 2;          // 0..63
    const int lk = (tid & 3) * 4;     // 0,4,8,12

    for (int k0 = 0; k0 < DD; k0 += BK) {
        // A tile: emb rows (gathered)
        {
            const float* src = emb + (size_t)sids[lm] * DD + k0 + lk;
            float4 a = *(const float4*)src;
            As[lk + 0][lm] = a.x; As[lk + 1][lm] = a.y;
            As[lk + 2][lm] = a.z; As[lk + 3][lm] = a.w;
        }
        // B tile: W1[h, k]
        {
            const float* src = W1 + (size_t)(bn + lm) * DD + k0 + lk;
            float4 b = *(const float4*)src;
            Bs[lk + 0][lm] = b.x; Bs[lk + 1][lm] = b.y;
            Bs[lk + 2][lm] = b.z; Bs[lk + 3][lm] = b.w;
        }
        __syncthreads();
#pragma unroll
        for (int k = 0; k < BK; k++) {
            float4 ra = *(const float4*)&As[k][ty * 4];
            float4 rb = *(const float4*)&Bs[k][tx * 4];
            float a[4] = {ra.x, ra.y, ra.z, ra.w};
            float b[4] = {rb.x, rb.y, rb.z, rb.w};
#pragma unroll
            for (int i = 0; i < 4; i++)
#pragma unroll
                for (int j = 0; j < 4; j++)
                    acc[i][j] = fmaf(a[i], b[j], acc[i][j]);
        }
        __syncthreads();
    }

    // epilogue: + b1, store
#pragma unroll
    for (int i = 0; i < 4; i++) {
        int m = bm + ty * 4 + i;
        float* dst = g_u + (size_t)m * HH + bn + tx * 4;
        float4 bv = *(const float4*)(b1 + bn + tx * 4);
        float4 o;
        o.x = acc[i][0] + bv.x; o.y = acc[i][1] + bv.y;
        o.z = acc[i][2] + bv.z; o.w = acc[i][3] + bv.w;
        *(float4*)dst = o;
    }
}

// ---------------- K2: LIF scan over T --------------------------------------
// grid: 8 blocks = (b in 0..3) x (half in 0..1); 512 threads; h = half*512+tid
#define TS 16
__global__ __launch_bounds__(512) void scan_kernel(const float* __restrict__ threshold)
{
    __shared__ float su[TS][512];
    const int b    = blockIdx.x >> 1;
    const int half = blockIdx.x & 1;
    const int tid  = threadIdx.x;
    const int h    = half * 512 + tid;

    const float thr = threshold[h];
    float m = 0.f;

    for (int t0 = 0; t0 < TT; t0 += TS) {
        // cooperative load TS x 512 tile (float4-coalesced)
#pragma unroll
        for (int j = 0; j < 4; j++) {
            int f4  = tid + j * 512;          // 0..2047
            int tt  = f4 >> 7;                // /128
            int hh4 = (f4 & 127) << 2;        // *4
            const float* src = g_u + ((size_t)(b * TT + t0 + tt) * HH) + half * 512 + hh4;
            *(float4*)&su[tt][hh4] = *(const float4*)src;
        }
        __syncthreads();
#pragma unroll
        for (int tt = 0; tt < TS; tt++) {
            m = fmaf(m, DECAYF, su[tt][tid]);
            if (m >= thr) {
                int row = b * TT + t0 + tt;
                int pos = atomicAdd(&g_cnt[row], 1);
                g_list[(size_t)row * HH + pos] = h;
                m = 0.f;
            }
        }
        __syncthreads();
    }
}

// ---------------- K3: logits = b2 + sparse column sums; fill tail -----------
__global__ __launch_bounds__(256) void fc2_kernel(
    const float* __restrict__ W2, const float* __restrict__ b2,
    float* __restrict__ out, long long out_size)
{
    long long limit = out_size < NLOGITS ? out_size : NLOGITS;
    unsigned int i4 = blockIdx.x * blockDim.x + threadIdx.x;
    long long e = (long long)i4 * 4;
    if (e < NLOGITS) {
        unsigned int eu = (unsigned int)e;
        unsigned int row = eu / VV;
        unsigned int v   = eu % VV;       // multiple of 4 (VV % 4 == 0)
        float4 r = *(const float4*)(b2 + v);
        int k = g_cnt[row];
        for (int s = 0; s < k; s++) {
            int h = g_list[(size_t)row * HH + s];
            const float* w = W2 + (size_t)v * HH + h;
            r.x += w[0];
            r.y += w[HH];
            r.z += w[2 * HH];
            r.w += w[3 * HH];
        }
        if (e + 4 <= limit) {
            *(float4*)(out + e) = r;
        } else {
            float vals[4] = {r.x, r.y, r.z, r.w};
            for (int j = 0; j < 4; j++)
                if (e + j < limit) out[e + j] = vals[j];
        }
    }
    // tail (avg_spikes, mem_out scalars -> 0)
    if (i4 == 0) {
        for (long long t = NLOGITS; t < out_size; t++) out[t] = 0.f;
    }
}

// ---------------- launcher ---------------------------------------------------
extern "C" void kernel_launch(void* const* d_in, const int* in_sizes, int n_in,
                              void* d_out, int out_size)
{
    const int*   ids = (const int*)  d_in[0];
    const float* emb = (const float*)d_in[1];
    const float* W1  = (const float*)d_in[2];
    const float* b1  = (const float*)d_in[3];
    const float* W2  = (const float*)d_in[4];
    const float* b2  = (const float*)d_in[5];
    const float* thr = (const float*)d_in[6];
    float* out = (float*)d_out;

    zero_cnt_kernel<<<(MM + 255) / 256, 256>>>();

    dim3 g1(HH / BN, MM / BM);   // (16, 32)
    fc1_kernel<<<g1, 256>>>(ids, emb, W1, b1);

    scan_kernel<<<BB * 2, 512>>>(thr);

    long long n4 = (NLOGITS + 3) / 4;
    int blocks = (int)((n4 + 255) / 256);
    fc2_kernel<<<blocks, 256>>>(W2, b2, out, (long long)out_size);
}

// round 2
// speedup vs baseline: 1.0009x; 1.0009x over previous
#include <cuda_runtime.h>
#include <cuda_bf16.h>
#include <cstdint>

// Problem dims
#define BB 4
#define TT 512
#define DD 512
#define HH 1024
#define VV 32000
#define MM (BB*TT)                 // 2048 rows
#define NLOGITS ((long long)MM * VV)  // 65,536,000

#define DECAYF 0.60653065971263342f  // exp(-1/2)

// ---------------- scratch (static device allocations are allowed) -----------
__device__ float g_u[MM * HH];        // fc1 output, 8 MB
__device__ int   g_cnt[MM];           // spikes per (b,t) row
__device__ int   g_list[MM * HH];     // spike h-indices per row (worst case full)

// ---------------- K0: zero the counters ------------------------------------
__global__ void zero_cnt_kernel() {
    int i = blockIdx.x * blockDim.x + threadIdx.x;
    if (i < MM) g_cnt[i] = 0;
}

// ---------------- K1: fused gather + fc1 SGEMM ------------------------------
// u[m, h] = sum_d emb[ids[m], d] * W1[h, d] + b1[h]
// BM=64, BN=64, BK=16, 256 threads, 4x4 per-thread tile
#define BM 64
#define BN 64
#define BK 16
__global__ __launch_bounds__(256) void fc1_kernel(
    const int* __restrict__ ids, const float* __restrict__ emb,
    const float* __restrict__ W1, const float* __restrict__ b1)
{
    __shared__ float As[BK][BM];
    __shared__ float Bs[BK][BN];
    __shared__ int   sids[BM];

    const int bn = blockIdx.x * BN;   // h offset
    const int bm = blockIdx.y * BM;   // row offset
    const int tid = threadIdx.x;
    const int tx = tid & 15;          // 0..15 -> 4 cols each
    const int ty = tid >> 4;          // 0..15 -> 4 rows each

    if (tid < BM) sids[tid] = ids[bm + tid];
    __syncthreads();

    float acc[4][4];
#pragma unroll
    for (int i = 0; i < 4; i++)
#pragma unroll
        for (int j = 0; j < 4; j++) acc[i][j] = 0.f;

    const int lm = tid >> 2;          // 0..63
    const int lk = (tid & 3) * 4;     // 0,4,8,12

    for (int k0 = 0; k0 < DD; k0 += BK) {
        // A tile: emb rows (gathered)
        {
            const float* src = emb + (size_t)sids[lm] * DD + k0 + lk;
            float4 a = *(const float4*)src;
            As[lk + 0][lm] = a.x; As[lk + 1][lm] = a.y;
            As[lk + 2][lm] = a.z; As[lk + 3][lm] = a.w;
        }
        // B tile: W1[h, k]
        {
            const float* src = W1 + (size_t)(bn + lm) * DD + k0 + lk;
            float4 b = *(const float4*)src;
            Bs[lk + 0][lm] = b.x; Bs[lk + 1][lm] = b.y;
            Bs[lk + 2][lm] = b.z; Bs[lk + 3][lm] = b.w;
        }
        __syncthreads();
#pragma unroll
        for (int k = 0; k < BK; k++) {
            float4 ra = *(const float4*)&As[k][ty * 4];
            float4 rb = *(const float4*)&Bs[k][tx * 4];
            float a[4] = {ra.x, ra.y, ra.z, ra.w};
            float b[4] = {rb.x, rb.y, rb.z, rb.w};
#pragma unroll
            for (int i = 0; i < 4; i++)
#pragma unroll
                for (int j = 0; j < 4; j++)
                    acc[i][j] = fmaf(a[i], b[j], acc[i][j]);
        }
        __syncthreads();
    }

    // epilogue: + b1, store
#pragma unroll
    for (int i = 0; i < 4; i++) {
        int m = bm + ty * 4 + i;
        float* dst = g_u + (size_t)m * HH + bn + tx * 4;
        float4 bv = *(const float4*)(b1 + bn + tx * 4);
        float4 o;
        o.x = acc[i][0] + bv.x; o.y = acc[i][1] + bv.y;
        o.z = acc[i][2] + bv.z; o.w = acc[i][3] + bv.w;
        *(float4*)dst = o;
    }
}

// ---------------- K2: LIF scan over T --------------------------------------
// grid: 8 blocks = (b in 0..3) x (half in 0..1); 512 threads; h = half*512+tid
#define TS 16
__global__ __launch_bounds__(512) void scan_kernel(const float* __restrict__ threshold)
{
    __shared__ float su[TS][512];
    const int b    = blockIdx.x >> 1;
    const int half = blockIdx.x & 1;
    const int tid  = threadIdx.x;
    const int h    = half * 512 + tid;

    const float thr = threshold[h];
    float m = 0.f;

    for (int t0 = 0; t0 < TT; t0 += TS) {
        // cooperative load TS x 512 tile (float4-coalesced)
#pragma unroll
        for (int j = 0; j < 4; j++) {
            int f4  = tid + j * 512;          // 0..2047
            int tt  = f4 >> 7;                // /128
            int hh4 = (f4 & 127) << 2;        // *4
            const float* src = g_u + ((size_t)(b * TT + t0 + tt) * HH) + half * 512 + hh4;
            *(float4*)&su[tt][hh4] = *(const float4*)src;
        }
        __syncthreads();
#pragma unroll
        for (int tt = 0; tt < TS; tt++) {
            m = fmaf(m, DECAYF, su[tt][tid]);
            if (m >= thr) {
                int row = b * TT + t0 + tt;
                int pos = atomicAdd(&g_cnt[row], 1);
                g_list[(size_t)row * HH + pos] = h;
                m = 0.f;
            }
        }
        __syncthreads();
    }
}

// ---------------- K3: logits = b2 + sparse column sums; fill tail -----------
__global__ __launch_bounds__(256) void fc2_kernel(
    const float* __restrict__ W2, const float* __restrict__ b2,
    float* __restrict__ out, long long out_size)
{
    long long limit = out_size < NLOGITS ? out_size : NLOGITS;
    unsigned int i4 = blockIdx.x * blockDim.x + threadIdx.x;
    long long e = (long long)i4 * 4;
    if (e < NLOGITS) {
        unsigned int eu = (unsigned int)e;
        unsigned int row = eu / VV;
        unsigned int v   = eu % VV;       // multiple of 4 (VV % 4 == 0)
        float4 r = *(const float4*)(b2 + v);
        int k = g_cnt[row];
        for (int s = 0; s < k; s++) {
            int h = g_list[(size_t)row * HH + s];
            const float* w = W2 + (size_t)v * HH + h;
            r.x += w[0];
            r.y += w[HH];
            r.z += w[2 * HH];
            r.w += w[3 * HH];
        }
        if (e + 4 <= limit) {
            *(float4*)(out + e) = r;
        } else {
            float vals[4] = {r.x, r.y, r.z, r.w};
            for (int j = 0; j < 4; j++)
                if (e + j < limit) out[e + j] = vals[j];
        }
    }
    // tail (avg_spikes, mem_out scalars -> 0)
    if (i4 == 0) {
        for (long long t = NLOGITS; t < out_size; t++) out[t] = 0.f;
    }
}

// ---------------- launcher ---------------------------------------------------
extern "C" void kernel_launch(void* const* d_in, const int* in_sizes, int n_in,
                              void* d_out, int out_size)
{
    const int*   ids = (const int*)  d_in[0];
    const float* emb = (const float*)d_in[1];
    const float* W1  = (const float*)d_in[2];
    const float* b1  = (const float*)d_in[3];
    const float* W2  = (const float*)d_in[4];
    const float* b2  = (const float*)d_in[5];
    const float* thr = (const float*)d_in[6];
    float* out = (float*)d_out;

    zero_cnt_kernel<<<(MM + 255) / 256, 256>>>();

    dim3 g1(HH / BN, MM / BM);   // (16, 32)
    fc1_kernel<<<g1, 256>>>(ids, emb, W1, b1);

    scan_kernel<<<BB * 2, 512>>>(thr);

    long long n4 = (NLOGITS + 3) / 4;
    int blocks = (int)((n4 + 255) / 256);
    fc2_kernel<<<blocks, 256>>>(W2, b2, out, (long long)out_size);
}

// round 3
// speedup vs baseline: 1.8409x; 1.8393x over previous
#include <cuda_runtime.h>
#include <cuda_bf16.h>
#include <mma.h>
#include <cstdint>

using namespace nvcuda;

// Problem dims
#define BB 4
#define TT 512
#define DD 512
#define HH 1024
#define VV 32000
#define MM (BB*TT)                    // 2048 rows
#define NLOGITS ((long long)MM * VV)  // 65,536,000

#define DECAYF 0.60653065971263342f   // exp(-1/2)

// ---------------- scratch ----------------------------------------------------
__device__ float         g_u[MM * HH];     // fc1 output (pre-bias), 8 MB
__device__ int           g_cnt[MM];        // spikes per (b,t) row
__device__ int           g_list[MM * HH];  // spike h-indices per row
__device__ __nv_bfloat16 g_W1b[HH * DD];   // bf16 W1
__device__ __nv_bfloat16 g_Ab[MM * DD];    // bf16 gathered embeddings

// ---------------- K0: zero counters + convert to bf16 ------------------------
#define W1Q (HH*DD/4)
#define AQ  (MM*DD/4)
__global__ __launch_bounds__(256) void prep_kernel(
    const int* __restrict__ ids, const float* __restrict__ emb,
    const float* __restrict__ W1)
{
    int i = blockIdx.x * blockDim.x + threadIdx.x;
    if (i < MM) g_cnt[i] = 0;
    if (i < W1Q) {
        float4 v = ((const float4*)W1)[i];
        __nv_bfloat162* dst = (__nv_bfloat162*)(g_W1b) + i * 2;
        dst[0] = __float22bfloat162_rn(make_float2(v.x, v.y));
        dst[1] = __float22bfloat162_rn(make_float2(v.z, v.w));
    } else if (i < W1Q + AQ) {
        int e4 = i - W1Q;
        int m  = e4 >> 7;              // / (DD/4)
        int dq = e4 & 127;             // % (DD/4)
        float4 v = *(const float4*)(emb + (size_t)ids[m] * DD + dq * 4);
        __nv_bfloat162* dst = (__nv_bfloat162*)(g_Ab + (size_t)m * DD + dq * 4);
        dst[0] = __float22bfloat162_rn(make_float2(v.x, v.y));
        dst[1] = __float22bfloat162_rn(make_float2(v.z, v.w));
    }
}

// ---------------- K1: bf16 tensor-core GEMM  u = Ab @ W1b^T ------------------
// C[m,h] = sum_d Ab[m,d] * W1b[h,d].  Block tile 128x128, k-chunk 32.
// 8 warps: warp grid 2(m) x 4(n), warp tile 64x32 = 4x2 wmma 16x16x16 frags.
#define GBM 128
#define GBN 128
#define GKC 32
#define KPAD 40   // 80B row pitch: 16B-aligned, LDSM conflict-free

__global__ __launch_bounds__(256) void fc1_kernel()
{
    __shared__ __align__(16) __nv_bfloat16 As[GBM][KPAD];
    __shared__ __align__(16) __nv_bfloat16 Bs[GBN][KPAD];

    const int bn  = blockIdx.x * GBN;
    const int bm  = blockIdx.y * GBM;
    const int tid = threadIdx.x;
    const int wid = tid >> 5;
    const int wm  = wid & 1;    // 0..1
    const int wn  = wid >> 1;   // 0..3

    wmma::fragment<wmma::accumulator, 16, 16, 16, float> c[4][2];
#pragma unroll
    for (int i = 0; i < 4; i++)
#pragma unroll
        for (int j = 0; j < 2; j++) wmma::fill_fragment(c[i][j], 0.f);

    for (int k0 = 0; k0 < DD; k0 += GKC) {
        // stage A (128 x 32) and B (128 x 32) bf16 tiles, 16B per thread x2 each
#pragma unroll
        for (int it = 0; it < 2; it++) {
            int idx = tid + it * 256;        // 0..511
            int row = idx >> 2;              // 0..127
            int kq  = (idx & 3) * 8;         // 0,8,16,24
            *(uint4*)&As[row][kq] =
                *(const uint4*)(g_Ab + (size_t)(bm + row) * DD + k0 + kq);
            *(uint4*)&Bs[row][kq] =
                *(const uint4*)(g_W1b + (size_t)(bn + row) * DD + k0 + kq);
        }
        __syncthreads();

#pragma unroll
        for (int kk = 0; kk < GKC; kk += 16) {
            wmma::fragment<wmma::matrix_a, 16, 16, 16, __nv_bfloat16, wmma::row_major> a[4];
            wmma::fragment<wmma::matrix_b, 16, 16, 16, __nv_bfloat16, wmma::col_major> b[2];
#pragma unroll
            for (int i = 0; i < 4; i++)
                wmma::load_matrix_sync(a[i], &As[wm * 64 + i * 16][kk], KPAD);
#pragma unroll
            for (int j = 0; j < 2; j++)
                wmma::load_matrix_sync(b[j], &Bs[wn * 32 + j * 16][kk], KPAD);
#pragma unroll
            for (int i = 0; i < 4; i++)
#pragma unroll
                for (int j = 0; j < 2; j++)
                    wmma::mma_sync(c[i][j], a[i], b[j], c[i][j]);
        }
        __syncthreads();
    }

    // epilogue: raw GEMM out (bias folded into scan)
#pragma unroll
    for (int i = 0; i < 4; i++)
#pragma unroll
        for (int j = 0; j < 2; j++) {
            float* dst = g_u + (size_t)(bm + wm * 64 + i * 16) * HH
                             + bn + wn * 32 + j * 16;
            wmma::store_matrix_sync(dst, c[i][j], HH, wmma::mem_row_major);
        }
}

// ---------------- K2: LIF scan over T ----------------------------------------
// 32 blocks = 4 batches x 8 h-chunks(128); 128 threads; bias added here.
#define TS 32
__global__ __launch_bounds__(128) void scan_kernel(
    const float* __restrict__ threshold, const float* __restrict__ b1)
{
    __shared__ float su[TS][128];
    const int b   = blockIdx.x >> 3;
    const int hc  = blockIdx.x & 7;
    const int tid = threadIdx.x;
    const int h   = hc * 128 + tid;

    const float thr = threshold[h];
    const float bia = b1[h];
    float m = 0.f;

    for (int t0 = 0; t0 < TT; t0 += TS) {
        // cooperative load TS x 128 tile (float4-coalesced)
#pragma unroll
        for (int j = 0; j < 8; j++) {
            int f4  = tid + j * 128;          // 0..1023
            int tt  = f4 >> 5;                // 32 float4 per row
            int hh4 = (f4 & 31) << 2;
            const float* src = g_u + (size_t)(b * TT + t0 + tt) * HH + hc * 128 + hh4;
            *(float4*)&su[tt][hh4] = *(const float4*)src;
        }
        __syncthreads();
#pragma unroll
        for (int tt = 0; tt < TS; tt++) {
            m = fmaf(m, DECAYF, su[tt][tid] + bia);
            if (m >= thr) {
                int row = b * TT + t0 + tt;
                int pos = atomicAdd(&g_cnt[row], 1);
                g_list[(size_t)row * HH + pos] = h;
                m = 0.f;
            }
        }
        __syncthreads();
    }
}

// ---------------- K3: logits = b2 + sparse column sums; fill tail ------------
__global__ __launch_bounds__(256) void fc2_kernel(
    const float* __restrict__ W2, const float* __restrict__ b2,
    float* __restrict__ out, long long out_size)
{
    long long limit = out_size < NLOGITS ? out_size : NLOGITS;
    unsigned int i4 = blockIdx.x * blockDim.x + threadIdx.x;
    long long e = (long long)i4 * 4;
    if (e < NLOGITS) {
        unsigned int eu  = (unsigned int)e;
        unsigned int row = eu / VV;
        unsigned int v   = eu % VV;       // multiple of 4
        float4 r = *(const float4*)(b2 + v);
        int k = g_cnt[row];
        for (int s = 0; s < k; s++) {
            int h = g_list[(size_t)row * HH + s];
            const float* w = W2 + (size_t)v * HH + h;
            r.x += w[0];
            r.y += w[HH];
            r.z += w[2 * HH];
            r.w += w[3 * HH];
        }
        if (e + 4 <= limit) {
            __stcs((float4*)(out + e), r);
        } else {
            float vals[4] = {r.x, r.y, r.z, r.w};
            for (int j = 0; j < 4; j++)
                if (e + j < limit) out[e + j] = vals[j];
        }
    }
    // tail scalars (avg_spikes, mem_out) -> 0
    if (i4 == 0) {
        for (long long t = NLOGITS; t < out_size; t++) out[t] = 0.f;
    }
}

// ---------------- launcher ---------------------------------------------------
extern "C" void kernel_launch(void* const* d_in, const int* in_sizes, int n_in,
                              void* d_out, int out_size)
{
    const int*   ids = (const int*)  d_in[0];
    const float* emb = (const float*)d_in[1];
    const float* W1  = (const float*)d_in[2];
    const float* b1  = (const float*)d_in[3];
    const float* W2  = (const float*)d_in[4];
    const float* b2  = (const float*)d_in[5];
    const float* thr = (const float*)d_in[6];
    float* out = (float*)d_out;

    int prep_total = W1Q + AQ;                       // 393,216
    prep_kernel<<<(prep_total + 255) / 256, 256>>>(ids, emb, W1);

    dim3 g1(HH / GBN, MM / GBM);                     // (8, 16)
    fc1_kernel<<<g1, 256>>>();

    scan_kernel<<<32, 128>>>(thr, b1);

    long long n4 = (NLOGITS + 3) / 4;
    int blocks = (int)((n4 + 255) / 256);
    fc2_kernel<<<blocks, 256>>>(W2, b2, out, (long long)out_size);
}